// round 9
// baseline (speedup 1.0000x reference)
#include <cuda_runtime.h>
#include <math.h>

#define HOPSZ 512
#define MAX_NHAR 128
#define NWPAD 4416              // >= max winsize 4410, multiple of 16
#define PH 3.4061215800872442e-19f   // 2*pi / 2^64
#define NBLOCKS 592             // 4 blocks/SM * 148 SMs

typedef unsigned long long ull;

__device__ int g_ctr;

__global__ void reset_ctr_kernel() { g_ctr = 0; }

__forceinline__ __device__ ull pk2(float lo, float hi) {
    ull r; asm("mov.b64 %0, {%1,%2};" : "=l"(r) : "f"(lo), "f"(hi)); return r;
}
__forceinline__ __device__ ull fma2(ull a, ull b, ull c) {
    ull d; asm("fma.rn.f32x2 %0, %1, %2, %3;" : "=l"(d) : "l"(a), "l"(b), "l"(c)); return d;
}
__forceinline__ __device__ ull mul2(ull a, ull b) {
    ull d; asm("mul.rn.f32x2 %0, %1, %2;" : "=l"(d) : "l"(a), "l"(b)); return d;
}
__forceinline__ __device__ float hadd2(ull v) {
    float lo, hi; asm("mov.b64 {%0,%1}, %2;" : "=f"(lo), "=f"(hi) : "l"(v)); return lo + hi;
}

__global__ __launch_bounds__(256, 4) void czt_persistent4_kernel(
    const float* __restrict__ x,
    const float* __restrict__ f0g,
    float* __restrict__ out,
    int T, int nframes)
{
    __shared__ __align__(16) float xw[NWPAD];
    __shared__ float red_r[256], red_i[256];
    __shared__ ull phi_q_s;
    __shared__ int frame_s, nhar_s, winsize_s;

    const int tid = threadIdx.x;

    while (true) {
        // ---- fetch next frame + scalar setup (only fp64 in kernel) ----
        if (tid == 0) {
            int f = atomicAdd(&g_ctr, 1);
            frame_s = f;
            if (f < nframes) {
                double f0 = (double)f0g[f];
                if (f0 < 40.0) f0 = 40.0;
                double r = 44100.0 / f0;
                int nh = (int)floor(r * 0.5);
                if (nh > MAX_NHAR) nh = MAX_NHAR;
                if (nh < 1) nh = 1;
                int ws = 2 * (int)rint(r * 2.0);
                if (ws > 4410) ws = 4410;
                nhar_s = nh;
                winsize_s = ws;
                phi_q_s = (ull)__double2ll_rn((f0 / 44100.0) * 18446744073709551616.0);
            }
        }
        __syncthreads();

        const int frame = frame_s;
        if (frame >= nframes) return;          // uniform exit

        const int nhar = nhar_s;
        const int winsize = winsize_s;
        const ull phi_q = phi_q_s;

        // ---- phase 1: windowed frame -> smem (single-cos Blackman) ----
        const int base = frame * HOPSZ - (winsize >> 1);
        const float invn = 1.0f / (float)winsize;
        const int wsz16 = (winsize + 15) & ~15;
        for (int j = tid; j < wsz16; j += 256) {
            float v = 0.0f;
            if (j < winsize) {
                int gi = base + j;
                float xv = (gi >= 0 && gi < T) ? x[gi] : 0.0f;
                float a = 6.28318530717958647692f * ((float)j * invn);
                float c = __cosf(a);
                // 0.42 - 0.5 c + 0.08 (2c^2 - 1) = 0.34 - 0.5 c + 0.16 c^2
                float w = fmaf(c, fmaf(0.16f, c, -0.5f), 0.34f);
                v = xv * w;
            }
            xw[j] = v;
        }
        __syncthreads();

        // ---- balanced (k, segment) mapping: all 256 threads active ----
        const int k = tid % nhar;
        const int s = tid / nhar;
        const int nsegk = (255 - k) / nhar + 1;

        const ull om_q = phi_q * (ull)(k + 1);

        // twiddles u_d = e^{-i om d}, d=0..15, packed pairwise
        float ccv[16], nsv[16];
        ccv[0] = 1.0f; nsv[0] = 0.0f;
        #pragma unroll
        for (int d = 1; d < 16; ++d) {
            float a = (float)(long long)(om_q * (ull)d) * PH;
            float sn, cs; __sincosf(a, &sn, &cs);
            ccv[d] = cs; nsv[d] = -sn;
        }
        ull C0 = pk2(ccv[0], ccv[1]),  C1 = pk2(ccv[2], ccv[3]);
        ull C2 = pk2(ccv[4], ccv[5]),  C3 = pk2(ccv[6], ccv[7]);
        ull C4 = pk2(ccv[8], ccv[9]),  C5 = pk2(ccv[10], ccv[11]);
        ull C6 = pk2(ccv[12], ccv[13]), C7 = pk2(ccv[14], ccv[15]);
        ull S0 = pk2(nsv[0], nsv[1]),  S1 = pk2(nsv[2], nsv[3]);
        ull S2 = pk2(nsv[4], nsv[5]),  S3 = pk2(nsv[6], nsv[7]);
        ull S4 = pk2(nsv[8], nsv[9]),  S5 = pk2(nsv[10], nsv[11]);
        ull S6 = pk2(nsv[12], nsv[13]), S7 = pk2(nsv[14], nsv[15]);

        float w16r, w16i;
        {
            float a = (float)(long long)(om_q * 16ull) * PH;
            float sn, cs; __sincosf(a, &sn, &cs);
            w16r = cs; w16i = -sn;
        }

        // segment bounds (multiples of 16)
        const int Lc = (((wsz16 + nsegk - 1) / nsegk) + 15) & ~15;
        int a0 = s * Lc;
        int b0 = a0 + Lc; if (b0 > wsz16) b0 = wsz16;

        ull ACCR = 0ull, ACCI = 0ull;          // packed f32x2 accumulators

        for (int a2 = a0; a2 < b0; a2 += 512) {    // exact Q64 rotor resync
            float wr, wi;
            {
                float a = (float)(long long)(om_q * (ull)a2) * PH;
                float sn, cs; __sincosf(a, &sn, &cs);
                wr = cs; wi = -sn;
            }
            int bend = a2 + 512; if (bend > b0) bend = b0;
            #pragma unroll 4
            for (int j0 = a2; j0 < bend; j0 += 16) {
                ulonglong2 qa = *(const ulonglong2*)(xw + j0);
                ulonglong2 qb = *(const ulonglong2*)(xw + j0 + 4);
                ulonglong2 qc = *(const ulonglong2*)(xw + j0 + 8);
                ulonglong2 qd = *(const ulonglong2*)(xw + j0 + 12);
                // packed partials over 16 samples
                ull mr = mul2(qa.x, C0);
                mr = fma2(qa.y, C1, mr);
                mr = fma2(qb.x, C2, mr);
                mr = fma2(qb.y, C3, mr);
                mr = fma2(qc.x, C4, mr);
                mr = fma2(qc.y, C5, mr);
                mr = fma2(qd.x, C6, mr);
                mr = fma2(qd.y, C7, mr);
                ull mi = mul2(qa.x, S0);
                mi = fma2(qa.y, S1, mi);
                mi = fma2(qb.x, S2, mi);
                mi = fma2(qb.y, S3, mi);
                mi = fma2(qc.x, S4, mi);
                mi = fma2(qc.y, S5, mi);
                mi = fma2(qd.x, S6, mi);
                mi = fma2(qd.y, S7, mi);
                // fold with broadcast-packed block twiddle (wr, wi = e^{-i om j0})
                ull WRp = pk2(wr, wr);
                ull WIp = pk2(wi, wi);
                ull NWIp = pk2(-wi, -wi);
                ACCR = fma2(mr, WRp, ACCR); ACCR = fma2(mi, NWIp, ACCR);
                ACCI = fma2(mi, WRp, ACCI); ACCI = fma2(mr, WIp, ACCI);
                // W *= W16
                float nr = fmaf(wr, w16r, -(wi * w16i));
                float ni = fmaf(wr, w16i,   wi * w16r);
                wr = nr; wi = ni;
            }
        }

        red_r[tid] = hadd2(ACCR);
        red_i[tid] = hadd2(ACCI);
        __syncthreads();

        // ---- epilogue: gather segments per harmonic, scale, write ----
        if (tid < nhar) {
            float rr = 0.0f, ri = 0.0f;
            for (int u = tid; u < 256; u += nhar) { rr += red_r[u]; ri += red_i[u]; }
            float scale = 2.381f / (float)((winsize >> 1) + 1);
            float yr = rr * scale, yi = ri * scale;
            out[tid * nframes + frame] = sqrtf(yr * yr + yi * yi);
            out[(MAX_NHAR + tid) * nframes + frame] = atan2f(yi, yr);
        } else if (tid < MAX_NHAR) {
            out[tid * nframes + frame] = 0.0f;
            out[(MAX_NHAR + tid) * nframes + frame] = 0.0f;
        }
        __syncthreads();   // protect smem reuse across frames
    }
}

extern "C" void kernel_launch(void* const* d_in, const int* in_sizes, int n_in,
                              void* d_out, int out_size) {
    const float* x  = (const float*)d_in[0];
    const float* f0 = (const float*)d_in[1];
    float* out = (float*)d_out;
    int T = in_sizes[0];
    int nframes = in_sizes[1];
    reset_ctr_kernel<<<1, 1>>>();
    czt_persistent4_kernel<<<NBLOCKS, 256>>>(x, f0, out, T, nframes);
}

// round 11
// speedup vs baseline: 1.0873x; 1.0873x over previous
#include <cuda_runtime.h>
#include <math.h>

#define HOPSZ 512
#define MAX_NHAR 128
#define NWPAD 4416              // >= max winsize 4410, multiple of 16
#define PH 3.4061215800872442e-19f   // 2*pi / 2^64

typedef unsigned long long ull;

__forceinline__ __device__ ull pk2(float lo, float hi) {
    ull r; asm("mov.b64 %0, {%1,%2};" : "=l"(r) : "f"(lo), "f"(hi)); return r;
}
__forceinline__ __device__ ull fma2(ull a, ull b, ull c) {
    ull d; asm("fma.rn.f32x2 %0, %1, %2, %3;" : "=l"(d) : "l"(a), "l"(b), "l"(c)); return d;
}
__forceinline__ __device__ ull mul2(ull a, ull b) {
    ull d; asm("mul.rn.f32x2 %0, %1, %2;" : "=l"(d) : "l"(a), "l"(b)); return d;
}
__forceinline__ __device__ float hadd2(ull v) {
    float lo, hi; asm("mov.b64 {%0,%1}, %2;" : "=f"(lo), "=f"(hi) : "l"(v)); return lo + hi;
}

__global__ __launch_bounds__(256, 4) void czt_uniform_kernel(
    const float* __restrict__ x,
    const float* __restrict__ f0g,
    float* __restrict__ out,
    int T, int nframes)
{
    __shared__ __align__(16) float xw[NWPAD];
    __shared__ float red_r[256], red_i[256];
    __shared__ ull phi_q_s;
    __shared__ int nhar_s, winsize_s;

    const int frame = blockIdx.x;
    const int tid = threadIdx.x;

    // ---- only fp64 in the kernel: exact reference scalar semantics ----
    if (tid == 0) {
        double f0 = (double)f0g[frame];
        if (f0 < 40.0) f0 = 40.0;
        double r = 44100.0 / f0;
        int nh = (int)floor(r * 0.5);
        if (nh > MAX_NHAR) nh = MAX_NHAR;
        if (nh < 1) nh = 1;
        int ws = 2 * (int)rint(r * 2.0);
        if (ws > 4410) ws = 4410;
        nhar_s = nh;
        winsize_s = ws;
        phi_q_s = (ull)__double2ll_rn((f0 / 44100.0) * 18446744073709551616.0);
    }
    __syncthreads();

    const int nhar = nhar_s;
    const int winsize = winsize_s;
    const ull phi_q = phi_q_s;

    // ---- phase 1: windowed frame -> smem (single-cos Blackman) ----
    const int base = frame * HOPSZ - (winsize >> 1);
    const float invn = 1.0f / (float)winsize;
    const int wsz16 = (winsize + 15) & ~15;
    for (int j = tid; j < wsz16; j += 256) {
        float v = 0.0f;
        if (j < winsize) {
            int gi = base + j;
            float xv = (gi >= 0 && gi < T) ? x[gi] : 0.0f;
            float a = 6.28318530717958647692f * ((float)j * invn);
            float c = __cosf(a);
            // 0.42 - 0.5 c + 0.08 (2c^2 - 1) = 0.34 - 0.5 c + 0.16 c^2
            float w = fmaf(c, fmaf(0.16f, c, -0.5f), 0.34f);
            v = xv * w;
        }
        xw[j] = v;
    }
    __syncthreads();

    // ---- warp-uniform mapping: thread = (k = tid&127, half = tid>>7) ----
    // All 128 harmonics computed; k >= nhar masked at epilogue.
    const int k = tid & (MAX_NHAR - 1);
    const int half = tid >> 7;                 // warp-uniform

    const ull om_q = phi_q * (ull)(k + 1);

    // twiddles u_d = e^{-i om d}, d=0..15, packed pairwise
    float ccv[16], nsv[16];
    ccv[0] = 1.0f; nsv[0] = 0.0f;
    #pragma unroll
    for (int d = 1; d < 16; ++d) {
        float a = (float)(long long)(om_q * (ull)d) * PH;
        float sn, cs; __sincosf(a, &sn, &cs);
        ccv[d] = cs; nsv[d] = -sn;
    }
    ull C0 = pk2(ccv[0], ccv[1]),  C1 = pk2(ccv[2], ccv[3]);
    ull C2 = pk2(ccv[4], ccv[5]),  C3 = pk2(ccv[6], ccv[7]);
    ull C4 = pk2(ccv[8], ccv[9]),  C5 = pk2(ccv[10], ccv[11]);
    ull C6 = pk2(ccv[12], ccv[13]), C7 = pk2(ccv[14], ccv[15]);
    ull S0 = pk2(nsv[0], nsv[1]),  S1 = pk2(nsv[2], nsv[3]);
    ull S2 = pk2(nsv[4], nsv[5]),  S3 = pk2(nsv[6], nsv[7]);
    ull S4 = pk2(nsv[8], nsv[9]),  S5 = pk2(nsv[10], nsv[11]);
    ull S6 = pk2(nsv[12], nsv[13]), S7 = pk2(nsv[14], nsv[15]);

    float w16r, w16i;
    {
        float a = (float)(long long)(om_q * 16ull) * PH;
        float sn, cs; __sincosf(a, &sn, &cs);
        w16r = cs; w16i = -sn;
    }

    // uniform half-split (multiples of 16) — same for every thread in block
    const int Lc = ((wsz16 >> 1) + 15) & ~15;
    const int a0 = half ? Lc : 0;
    const int b0 = half ? wsz16 : Lc;

    ull ACCR = 0ull, ACCI = 0ull;              // packed f32x2 accumulators

    for (int a2 = a0; a2 < b0; a2 += 512) {    // exact Q64 rotor resync
        float wr, wi;
        {
            float a = (float)(long long)(om_q * (ull)a2) * PH;
            float sn, cs; __sincosf(a, &sn, &cs);
            wr = cs; wi = -sn;
        }
        int bend = a2 + 512; if (bend > b0) bend = b0;
        #pragma unroll 4
        for (int j0 = a2; j0 < bend; j0 += 16) {
            ulonglong2 qa = *(const ulonglong2*)(xw + j0);
            ulonglong2 qb = *(const ulonglong2*)(xw + j0 + 4);
            ulonglong2 qc = *(const ulonglong2*)(xw + j0 + 8);
            ulonglong2 qd = *(const ulonglong2*)(xw + j0 + 12);
            // packed partials over 16 samples
            ull mr = mul2(qa.x, C0);
            mr = fma2(qa.y, C1, mr);
            mr = fma2(qb.x, C2, mr);
            mr = fma2(qb.y, C3, mr);
            mr = fma2(qc.x, C4, mr);
            mr = fma2(qc.y, C5, mr);
            mr = fma2(qd.x, C6, mr);
            mr = fma2(qd.y, C7, mr);
            ull mi = mul2(qa.x, S0);
            mi = fma2(qa.y, S1, mi);
            mi = fma2(qb.x, S2, mi);
            mi = fma2(qb.y, S3, mi);
            mi = fma2(qc.x, S4, mi);
            mi = fma2(qc.y, S5, mi);
            mi = fma2(qd.x, S6, mi);
            mi = fma2(qd.y, S7, mi);
            // fold with broadcast-packed block twiddle (wr, wi = e^{-i om j0})
            ull WRp = pk2(wr, wr);
            ull WIp = pk2(wi, wi);
            ull NWIp = pk2(-wi, -wi);
            ACCR = fma2(mr, WRp, ACCR); ACCR = fma2(mi, NWIp, ACCR);
            ACCI = fma2(mi, WRp, ACCI); ACCI = fma2(mr, WIp, ACCI);
            // W *= W16
            float nr = fmaf(wr, w16r, -(wi * w16i));
            float ni = fmaf(wr, w16i,   wi * w16r);
            wr = nr; wi = ni;
        }
    }

    red_r[tid] = hadd2(ACCR);
    red_i[tid] = hadd2(ACCI);
    __syncthreads();

    // ---- epilogue: combine halves, mask k >= nhar, scale, write ----
    if (tid < MAX_NHAR) {
        float ampl = 0.0f, phs = 0.0f;
        if (tid < nhar) {
            float rr = red_r[tid] + red_r[tid + 128];
            float ri = red_i[tid] + red_i[tid + 128];
            float scale = 2.381f / (float)((winsize >> 1) + 1);
            float yr = rr * scale, yi = ri * scale;
            ampl = sqrtf(yr * yr + yi * yi);
            phs = atan2f(yi, yr);
        }
        out[tid * nframes + frame] = ampl;
        out[(MAX_NHAR + tid) * nframes + frame] = phs;
    }
}

extern "C" void kernel_launch(void* const* d_in, const int* in_sizes, int n_in,
                              void* d_out, int out_size) {
    const float* x  = (const float*)d_in[0];
    const float* f0 = (const float*)d_in[1];
    float* out = (float*)d_out;
    int T = in_sizes[0];
    int nframes = in_sizes[1];
    czt_uniform_kernel<<<nframes, 256>>>(x, f0, out, T, nframes);
}